// round 16
// baseline (speedup 1.0000x reference)
#include <cuda_runtime.h>
#include <cuda_fp16.h>
#include <cstdint>

// ---------------- fixed problem sizes ----------------
#define B_   4
#define T_   2048
#define S_   4096
#define KD   512
#define MQ_  (B_*T_)    // 8192
#define MK_  (B_*S_)    // 16384

// ---------------- GEMM tiling ----------------
#define BN 128
#define BK 64
#define MSPLIT 4
#define CONV_BLOCKS ((MQ_ + MK_) / 8)       // 3072
#define MCVT_BLOCKS ((KD * KD / 4) / 256)   // 256

// fused_prep block ranges
#define PREP_GEMM    64                     // 4 z * 4 mt * 4 nt
#define PREP_BIAS0   64
#define PREP_CONV0   80
#define PREP_MCVT0   (80 + CONV_BLOCKS)     // 3152
#define PREP_TOTAL   (PREP_MCVT0 + MCVT_BLOCKS)  // 3408
#define NCONS        (CONV_BLOCKS + MCVT_BLOCKS) // 3328

// ---------------- scratch ----------------
__device__ __half g_xq16[MQ_ * KD];
__device__ __half g_xk16[MK_ * KD];
__device__ float  g_Mf[MSPLIT * KD * KD];
__device__ __half g_M  [KD * KD];
__device__ __half g_Y  [MQ_ * KD];
__device__ float  g_u  [MQ_];
__device__ float  g_v  [MK_];
__device__ float  g_wu [KD];
__device__ float  g_wv [KD];
__device__ float  g_c;
__device__ int    g_cntA;   // M-GEMM producers done (64)
__device__ int    g_cntB;   // bias producers done (16)
__device__ int    g_done;   // consumers done (resets counters)

// ---------------- helpers ----------------
#define SWZ(o) ((o) ^ (((o) >> 3) & 0x70))

__device__ __forceinline__ uint32_t smem_u32(const void* p) {
    uint32_t a;
    asm("{ .reg .u64 t; cvta.to.shared.u64 t, %1; cvt.u32.u64 %0, t; }"
        : "=r"(a) : "l"(p));
    return a;
}

__device__ __forceinline__ void cp16(uint32_t s, const void* g) {
    asm volatile("cp.async.cg.shared.global [%0], [%1], 16;" :: "r"(s), "l"(g));
}
#define CP_COMMIT() asm volatile("cp.async.commit_group;" ::: "memory")
#define CP_WAIT0()  asm volatile("cp.async.wait_group 0;" ::: "memory")
#define CP_WAIT1()  asm volatile("cp.async.wait_group 1;" ::: "memory")

__device__ __forceinline__ void ldsm4(uint32_t* r, uint32_t addr) {
    asm volatile("ldmatrix.sync.aligned.m8n8.x4.shared.b16 {%0,%1,%2,%3}, [%4];"
                 : "=r"(r[0]), "=r"(r[1]), "=r"(r[2]), "=r"(r[3]) : "r"(addr));
}

__device__ __forceinline__ void mma16816(float* c, const uint32_t* a,
                                         uint32_t b0, uint32_t b1) {
    asm volatile(
        "mma.sync.aligned.m16n8k16.row.col.f32.f16.f16.f32 "
        "{%0,%1,%2,%3}, {%4,%5,%6,%7}, {%8,%9}, {%0,%1,%2,%3};"
        : "+f"(c[0]), "+f"(c[1]), "+f"(c[2]), "+f"(c[3])
        : "r"(a[0]), "r"(a[1]), "r"(a[2]), "r"(a[3]), "r"(b0), "r"(b1));
}

// release: whole block's stores published, then count
__device__ __forceinline__ void producer_arrive(int* cnt) {
    __syncthreads();
    if (threadIdx.x == 0) {
        __threadfence();
        atomicAdd(cnt, 1);
    }
}
// acquire: spin until n producers arrived
__device__ __forceinline__ void consumer_wait(int* cnt, int n) {
    if (threadIdx.x == 0) {
        while (atomicAdd(cnt, 0) < n) __nanosleep(64);
    }
    __syncthreads();
}

// ============ fused prep: M split-K GEMM + bias vectors + conv + M reduce ===
__global__ __launch_bounds__(256, 2) void fused_prep(
    const float* __restrict__ Wq32, const float* __restrict__ Wk32,
    const float* __restrict__ bq, const float* __restrict__ bk,
    const float4* __restrict__ xq, const float4* __restrict__ xk) {
    extern __shared__ char smem[];
    const int bid = blockIdx.x;
    const int tid = threadIdx.x;

    if (bid < PREP_GEMM) {
        // ---- M split-K GEMM slice: Mf[bz] += Wk^T slice * Wq^T slice ----
        const uint32_t sb = smem_u32(smem);
        const int bz = bid >> 4, mt = (bid >> 2) & 3, nt = bid & 3;
        const int wid = tid >> 5, l = tid & 31;
        const int wm = wid >> 2, wn = wid & 3;
        const int kStart = bz * (KD / MSPLIT);
        const int nch = (KD / MSPLIT) / BK;

        float acc[4][4][4];
#pragma unroll
        for (int i = 0; i < 4; ++i)
#pragma unroll
            for (int j = 0; j < 4; ++j)
#pragma unroll
                for (int c = 0; c < 4; ++c) acc[i][j][c] = 0.f;

        const int aRow = wm * 64 + (l & 15);
        const int aKsel = ((l >> 4) & 1) * 16;
        const int bRow = wn * 32 + (l & 7) + ((l >> 4) & 1) * 8;
        const int bKsel = ((l >> 3) & 1) * 16;
        const uint32_t sA = sb, sB = sb + 128 * 128;

        for (int ch = 0; ch < nch; ++ch) {
            const int k0 = kStart + ch * BK;
            __syncthreads();
#pragma unroll
            for (int t = 0; t < 32; ++t) {
                int idx = tid + t * 256;          // 8192 = 128 rows x 64 cols
                int r = idx & 127, c = idx >> 7;
                float va = Wk32[(size_t)(k0 + c) * KD + mt * 128 + r];
                float vb = Wq32[(size_t)(k0 + c) * KD + nt * 128 + r];
                *(__half*)(smem + SWZ((uint32_t)(r * 128 + c * 2))) =
                    __float2half(va);
                *(__half*)(smem + 128 * 128 +
                           SWZ((uint32_t)(r * 128 + c * 2))) = __float2half(vb);
            }
            __syncthreads();
            // B-preload pipeline
            uint32_t bfr[4][2][4];
#pragma unroll
            for (int ks = 0; ks < BK / 16; ++ks)
#pragma unroll
                for (int nb = 0; nb < 2; ++nb)
                    ldsm4(bfr[ks][nb],
                          sB + SWZ((uint32_t)((bRow + nb * 16) * 128 +
                                              ks * 32 + bKsel)));
#pragma unroll
            for (int ks = 0; ks < BK / 16; ++ks) {
                uint32_t afr[4][4];
#pragma unroll
                for (int mi = 0; mi < 4; ++mi)
                    ldsm4(afr[mi],
                          sA + SWZ((uint32_t)((aRow + mi * 16) * 128 +
                                              ks * 32 + aKsel)));
#pragma unroll
                for (int mi = 0; mi < 4; ++mi)
#pragma unroll
                    for (int ni = 0; ni < 4; ++ni)
                        mma16816(acc[mi][ni], afr[mi],
                                 bfr[ks][ni >> 1][(ni & 1) * 2],
                                 bfr[ks][ni >> 1][(ni & 1) * 2 + 1]);
            }
        }

        const int gid = l >> 2, tig = l & 3;
#pragma unroll
        for (int mi = 0; mi < 4; ++mi)
#pragma unroll
            for (int h = 0; h < 2; ++h) {
                const int row = mt * 128 + wm * 64 + mi * 16 + gid + h * 8;
#pragma unroll
                for (int ni = 0; ni < 4; ++ni) {
                    const int col = nt * BN + wn * 32 + ni * 8 + tig * 2;
                    float* dst = g_Mf + (size_t)bz * (KD * KD) +
                                 (size_t)row * KD + col;
                    dst[0] = acc[mi][ni][h * 2 + 0];
                    dst[1] = acc[mi][ni][h * 2 + 1];
                }
            }
        producer_arrive(&g_cntA);
    } else if (bid < PREP_CONV0) {
        // ---- parallel bias-vector prep (16 CTAs) ----
        const int id = bid - PREP_BIAS0;       // 0..15
        const bool isU = id < 8;
        const int base = (id & 7) * 64;
        const float* W = isU ? Wq32 : Wk32;
        const float* bb = isU ? bk : bq;
        float* dst = isU ? g_wu : g_wv;
        const int dl = tid & 63;
        const int js = tid >> 6;
        const int d = base + dl;
        float s = 0.f;
        const int j0 = js * 128;
#pragma unroll 16
        for (int j = 0; j < 128; ++j)
            s += bb[j0 + j] * W[(size_t)(j0 + j) * KD + d];
        __shared__ float red[4][64];
        red[js][dl] = s;
        __syncthreads();
        if (tid < 64)
            dst[base + tid] =
                (red[0][tid] + red[1][tid]) + (red[2][tid] + red[3][tid]);
        const int wid = tid >> 5, l = tid & 31;
        if (id == 0 && wid == 2) {
            float cs = 0.f;
#pragma unroll
            for (int jj = l; jj < KD; jj += 32) cs += bq[jj] * bk[jj];
#pragma unroll
            for (int o = 16; o; o >>= 1)
                cs += __shfl_xor_sync(0xffffffff, cs, o);
            if (l == 0) g_c = cs;
        }
        producer_arrive(&g_cntB);
    } else if (bid < PREP_MCVT0) {
        // ---- conv + row GEMV (gated on bias) ----
        consumer_wait(&g_cntB, 16);
        const int cb = bid - PREP_CONV0;
        const int gw = (cb * 256 + tid) >> 5;
        const int l = tid & 31;
        const bool isQ = gw < MQ_;
        const int r = isQ ? gw : gw - MQ_;
        const float4* src = isQ ? xq : xk;
        const float4* w4 = (const float4*)(isQ ? g_wu : g_wv);
        uint2* dst = (uint2*)(isQ ? g_xq16 : g_xk16);
        float dot = 0.f;
#pragma unroll
        for (int i = 0; i < 4; ++i) {
            const int idx = r * (KD / 4) + l + i * 32;
            float4 a = src[idx];
            float4 w = w4[l + i * 32];
            __half2 h01 = __floats2half2_rn(a.x, a.y);
            __half2 h23 = __floats2half2_rn(a.z, a.w);
            uint2 pkt;
            pkt.x = *(uint32_t*)&h01;
            pkt.y = *(uint32_t*)&h23;
            dst[idx] = pkt;
            dot += a.x * w.x + a.y * w.y + a.z * w.z + a.w * w.w;
        }
#pragma unroll
        for (int o = 16; o; o >>= 1) dot += __shfl_xor_sync(0xffffffff, dot, o);
        if (l == 0) {
            if (isQ) g_u[r] = (dot + g_c) * 0.015625f;
            else     g_v[r] = dot * 0.015625f;
        }
        // consumer bookkeeping + counter reset by last consumer
        __syncthreads();
        if (tid == 0) {
            int c = atomicAdd(&g_done, 1);
            if (c == NCONS - 1) { g_cntA = 0; g_cntB = 0; g_done = 0; }
        }
    } else {
        // ---- M partial reduce -> fp16 (gated on GEMM) ----
        consumer_wait(&g_cntA, PREP_GEMM);
        const int i = (bid - PREP_MCVT0) * 256 + tid;
        float4 s = *(const float4*)(g_Mf + (size_t)i * 4);
#pragma unroll
        for (int z = 1; z < MSPLIT; ++z) {
            float4 p =
                *(const float4*)(g_Mf + (size_t)z * (KD * KD) + (size_t)i * 4);
            s.x += p.x; s.y += p.y; s.z += p.z; s.w += p.w;
        }
        __half2* d = (__half2*)(g_M + (size_t)i * 4);
        d[0] = __floats2half2_rn(s.x, s.y);
        d[1] = __floats2half2_rn(s.z, s.w);
        __syncthreads();
        if (tid == 0) {
            int c = atomicAdd(&g_done, 1);
            if (c == NCONS - 1) { g_cntA = 0; g_cntB = 0; g_done = 0; }
        }
    }
}

// ---------------- fp16 GEMM:  D[m,n] = sum_k A[m,k] * B[n,k]  ----------------
// 256 thr, BN=128, 2-stage, B-preload pipeline.
// MODE 0: Y GEMM, BM=64  (grid 512). outH = D*scale (fp16)
// MODE 1: logits, BM=128 (frozen config). outF = D+u+v, mask -> -inf, stcs
template <int MODE>
__global__ __launch_bounds__(256, 2) void hgemm(
    const __half* __restrict__ A, const __half* __restrict__ Bm,
    __half* __restrict__ outH, float* __restrict__ outF,
    const unsigned char* __restrict__ mask,
    float scale, int aRows, int bRows, int outLd, int nch) {
    constexpr int BMv = (MODE == 0) ? 64 : 128;
    constexpr int MI = BMv / 32;
    constexpr int A_BYTES = BMv * 128;
    constexpr int STAGEB = A_BYTES + BN * 128;

    extern __shared__ char smem[];
    const uint32_t sb = smem_u32(smem);
    const int tid = threadIdx.x;
    const int wid = tid >> 5;
    const int l = tid & 31;
    const int wm = wid >> 2;
    const int wn = wid & 3;
    const int mt = blockIdx.x, nt = blockIdx.y, bz = blockIdx.z;

    const size_t aBase = ((size_t)bz * aRows + (size_t)mt * BMv) * KD;
    const size_t bBase = ((size_t)bz * bRows + (size_t)nt * BN) * KD;

    float* sv = (float*)(smem + 2 * STAGEB);
    unsigned char* sm = (unsigned char*)(smem + 2 * STAGEB + 512);
    if (MODE == 1 && tid < 128) {
        const size_t colg = (size_t)bz * S_ + (size_t)nt * BN + tid;
        sv[tid] = g_v[colg];
        sm[tid] = mask[colg];
    }

    float acc[MI][4][4];
#pragma unroll
    for (int i = 0; i < MI; ++i)
#pragma unroll
        for (int j = 0; j < 4; ++j)
#pragma unroll
            for (int c = 0; c < 4; ++c) acc[i][j][c] = 0.f;

    const int aRow = wm * (MI * 16) + (l & 15);
    const int aKsel = ((l >> 4) & 1) * 16;
    const int bRow = wn * 32 + (l & 7) + ((l >> 4) & 1) * 8;
    const int bKsel = ((l >> 3) & 1) * 16;

    auto mma_chunk = [&](uint32_t sA, uint32_t sB) {
        uint32_t bfr[4][2][4];
#pragma unroll
        for (int ks = 0; ks < BK / 16; ++ks)
#pragma unroll
            for (int nb = 0; nb < 2; ++nb)
                ldsm4(bfr[ks][nb],
                      sB + SWZ((uint32_t)((bRow + nb * 16) * 128 + ks * 32 +
                                          bKsel)));
#pragma unroll
        for (int ks = 0; ks < BK / 16; ++ks) {
            uint32_t afr[MI][4];
#pragma unroll
            for (int mi = 0; mi < MI; ++mi)
                ldsm4(afr[mi], sA + SWZ((uint32_t)((aRow + mi * 16) * 128 +
                                                   ks * 32 + aKsel)));
#pragma unroll
            for (int mi = 0; mi < MI; ++mi)
#pragma unroll
                for (int ni = 0; ni < 4; ++ni)
                    mma16816(acc[mi][ni], afr[mi],
                             bfr[ks][ni >> 1][(ni & 1) * 2],
                             bfr[ks][ni >> 1][(ni & 1) * 2 + 1]);
        }
    };

    auto load_tile = [&](int stg, int k0) {
        const uint32_t sA = sb + stg * STAGEB;
        const uint32_t sB = sA + A_BYTES;
#pragma unroll
        for (int t = 0; t < BMv / 32; ++t) {
            int i = tid + t * 256;
            int r = i >> 3, c = i & 7;
            cp16(sA + SWZ((uint32_t)(r * 128 + c * 16)),
                 A + aBase + (size_t)r * KD + k0 + c * 8);
        }
#pragma unroll
        for (int t = 0; t < 4; ++t) {
            int i = tid + t * 256;
            int r = i >> 3, c = i & 7;
            cp16(sB + SWZ((uint32_t)(r * 128 + c * 16)),
                 Bm + bBase + (size_t)r * KD + k0 + c * 8);
        }
    };

    load_tile(0, 0);
    CP_COMMIT();

    int stg = 0;
    for (int ch = 0; ch < nch; ++ch) {
        if (ch + 1 < nch) {
            load_tile(stg ^ 1, (ch + 1) * BK);
            CP_COMMIT();
            CP_WAIT1();
        } else {
            CP_WAIT0();
        }
        __syncthreads();
        mma_chunk(sb + stg * STAGEB, sb + stg * STAGEB + A_BYTES);
        __syncthreads();
        stg ^= 1;
    }

    // ---------------- epilogue ----------------
    const int gid = l >> 2, tig = l & 3;
#pragma unroll
    for (int mi = 0; mi < MI; ++mi) {
#pragma unroll
        for (int h = 0; h < 2; ++h) {
            const int row = mt * BMv + wm * (MI * 16) + mi * 16 + gid + h * 8;
            const size_t rowg = (size_t)bz * aRows + row;
            float uu = 0.f;
            if (MODE == 1) uu = g_u[rowg];
#pragma unroll
            for (int ni = 0; ni < 4; ++ni) {
                const int lcol = wn * 32 + ni * 8 + tig * 2;
                const int col = nt * BN + lcol;
                const float v0 = acc[mi][ni][h * 2 + 0];
                const float v1 = acc[mi][ni][h * 2 + 1];
                if (MODE == 0) {
                    *(__half2*)(outH + rowg * outLd + col) =
                        __floats2half2_rn(v0 * scale, v1 * scale);
                } else {
                    const float NEG_INF = __int_as_float(0xff800000);
                    float2 o;
                    o.x = sm[lcol + 0] ? NEG_INF : v0 + uu + sv[lcol + 0];
                    o.y = sm[lcol + 1] ? NEG_INF : v1 + uu + sv[lcol + 1];
                    __stcs((float2*)(outF + rowg * (size_t)S_ + col), o);
                }
            }
        }
    }
}

// ---------------- host launch ----------------
extern "C" void kernel_launch(void* const* d_in, const int* in_sizes, int n_in,
                              void* d_out, int out_size) {
    const float* query = (const float*)d_in[0];
    const float* keys = (const float*)d_in[1];
    const unsigned char* mask = (const unsigned char*)d_in[2];
    const float* q_w = (const float*)d_in[3];
    const float* q_b = (const float*)d_in[4];
    const float* k_w = (const float*)d_in[5];
    const float* k_b = (const float*)d_in[6];

    void *xq16, *xk16, *M, *Y;
    cudaGetSymbolAddress(&xq16, g_xq16);
    cudaGetSymbolAddress(&xk16, g_xk16);
    cudaGetSymbolAddress(&M, g_M);
    cudaGetSymbolAddress(&Y, g_Y);

    const int SMEMP = 2 * 128 * 128;                       // 32768 (prep GEMM)
    const int SMEM0 = 2 * (64 * 128 + BN * 128) + 640;     // 49792
    const int SMEM1 = 2 * (128 * 128 + BN * 128) + 640;    // 66176

    cudaFuncSetAttribute(hgemm<0>, cudaFuncAttributeMaxDynamicSharedMemorySize,
                         SMEM0);
    cudaFuncSetAttribute(hgemm<1>, cudaFuncAttributeMaxDynamicSharedMemorySize,
                         SMEM1);

    // 1) fused prep: M split-K GEMM + bias vectors + conv/GEMV + M reduce
    fused_prep<<<PREP_TOTAL, 256, SMEMP>>>(q_w, k_w, q_b, k_b,
                                           (const float4*)query,
                                           (const float4*)keys);

    // 2) Y = (xq @ M)/64   [8192 x 512] fp16, BM=64 -> 512 CTAs
    hgemm<0><<<dim3(MQ_ / 64, KD / BN, 1), 256, SMEM0>>>(
        (const __half*)xq16, (const __half*)M, (__half*)Y, nullptr, nullptr,
        0.015625f, MQ_, KD, KD, KD / BK);

    // 3) logits = Y @ xk^T + u[t] + v[s], masked   [4,2048,4096] fp32
    hgemm<1><<<dim3(T_ / 128, S_ / BN, B_), 256, SMEM1>>>(
        (const __half*)Y, (const __half*)xk16, nullptr, (float*)d_out,
        mask, 1.0f, T_, S_, S_, KD / BK);
}

// round 17
// speedup vs baseline: 1.0589x; 1.0589x over previous
#include <cuda_runtime.h>
#include <cuda_fp16.h>
#include <cstdint>

// ---------------- fixed problem sizes ----------------
#define B_   4
#define T_   2048
#define S_   4096
#define KD   512
#define MQ_  (B_*T_)    // 8192
#define MK_  (B_*S_)    // 16384

// ---------------- GEMM tiling ----------------
#define BN 128
#define BK 64
#define MSPLIT 4
#define CONV_BLOCKS ((MQ_ + MK_) / 8)       // 3072
#define MCVT_BLOCKS ((KD * KD / 4) / 256)   // 256

// ---------------- scratch ----------------
__device__ __half g_xq16[MQ_ * KD];
__device__ __half g_xk16[MK_ * KD];
__device__ float  g_Mf[MSPLIT * KD * KD];
__device__ __half g_M  [KD * KD];
__device__ __half g_Y  [MQ_ * KD];
__device__ float  g_u  [MQ_];
__device__ float  g_v  [MK_];
__device__ float  g_wu [KD];
__device__ float  g_wv [KD];
__device__ float  g_c;

// ---------------- helpers ----------------
#define SWZ(o) ((o) ^ (((o) >> 3) & 0x70))

__device__ __forceinline__ uint32_t smem_u32(const void* p) {
    uint32_t a;
    asm("{ .reg .u64 t; cvta.to.shared.u64 t, %1; cvt.u32.u64 %0, t; }"
        : "=r"(a) : "l"(p));
    return a;
}

__device__ __forceinline__ void cp16(uint32_t s, const void* g) {
    asm volatile("cp.async.cg.shared.global [%0], [%1], 16;" :: "r"(s), "l"(g));
}
#define CP_COMMIT() asm volatile("cp.async.commit_group;" ::: "memory")
#define CP_WAIT0()  asm volatile("cp.async.wait_group 0;" ::: "memory")
#define CP_WAIT1()  asm volatile("cp.async.wait_group 1;" ::: "memory")

__device__ __forceinline__ void ldsm4(uint32_t* r, uint32_t addr) {
    asm volatile("ldmatrix.sync.aligned.m8n8.x4.shared.b16 {%0,%1,%2,%3}, [%4];"
                 : "=r"(r[0]), "=r"(r[1]), "=r"(r[2]), "=r"(r[3]) : "r"(addr));
}

__device__ __forceinline__ void mma16816(float* c, const uint32_t* a,
                                         uint32_t b0, uint32_t b1) {
    asm volatile(
        "mma.sync.aligned.m16n8k16.row.col.f32.f16.f16.f32 "
        "{%0,%1,%2,%3}, {%4,%5,%6,%7}, {%8,%9}, {%0,%1,%2,%3};"
        : "+f"(c[0]), "+f"(c[1]), "+f"(c[2]), "+f"(c[3])
        : "r"(a[0]), "r"(a[1]), "r"(a[2]), "r"(a[3]), "r"(b0), "r"(b1));
}

// ---------- fused: fp32->fp16 convert + row GEMV (u, v)  AND  M reduce ----
__global__ void conv_fused(const float4* __restrict__ xq,
                           const float4* __restrict__ xk) {
    if (blockIdx.x >= CONV_BLOCKS) {
        const int i = (blockIdx.x - CONV_BLOCKS) * blockDim.x + threadIdx.x;
        float4 s = *(const float4*)(g_Mf + (size_t)i * 4);
#pragma unroll
        for (int z = 1; z < MSPLIT; ++z) {
            float4 p =
                *(const float4*)(g_Mf + (size_t)z * (KD * KD) + (size_t)i * 4);
            s.x += p.x; s.y += p.y; s.z += p.z; s.w += p.w;
        }
        __half2* d = (__half2*)(g_M + (size_t)i * 4);
        d[0] = __floats2half2_rn(s.x, s.y);
        d[1] = __floats2half2_rn(s.z, s.w);
        return;
    }
    const int gw = (blockIdx.x * blockDim.x + threadIdx.x) >> 5;
    const int l = threadIdx.x & 31;
    const bool isQ = gw < MQ_;
    const int r = isQ ? gw : gw - MQ_;
    const float4* src = isQ ? xq : xk;
    const float4* w4 = (const float4*)(isQ ? g_wu : g_wv);
    uint2* dst = (uint2*)(isQ ? g_xq16 : g_xk16);
    float dot = 0.f;
#pragma unroll
    for (int i = 0; i < 4; ++i) {
        const int idx = r * (KD / 4) + l + i * 32;
        float4 a = src[idx];
        float4 w = w4[l + i * 32];
        __half2 h01 = __floats2half2_rn(a.x, a.y);
        __half2 h23 = __floats2half2_rn(a.z, a.w);
        uint2 pkt;
        pkt.x = *(uint32_t*)&h01;
        pkt.y = *(uint32_t*)&h23;
        dst[idx] = pkt;                    // one 8B store per float4
        dot += a.x * w.x + a.y * w.y + a.z * w.z + a.w * w.w;
    }
#pragma unroll
    for (int o = 16; o; o >>= 1) dot += __shfl_xor_sync(0xffffffff, dot, o);
    if (l == 0) {
        if (isQ) g_u[r] = (dot + g_c) * 0.015625f;
        else     g_v[r] = dot * 0.015625f;
    }
}

// ---------------- fp16 GEMM:  D[m,n] = sum_k A[m,k] * B[n,k]  ----------------
// 256 thr, BN=128, 2-stage, B-preload pipeline.
// MODE 0: Y GEMM, BM=64, KPRE=2, 3 CTA/SM (higher occupancy for latency).
// MODE 1: logits, BM=128, KPRE=4 (frozen: instruction order identical).
// MODE 2: M split-K, BM=128, direct fp32 transposed loads + convert;
//         grid z slice MSPLIT: parallel bias-vector prep (wu, wv, c)
template <int MODE>
__global__ __launch_bounds__(256, (MODE == 0) ? 3 : 2) void hgemm(
    const __half* __restrict__ A, const __half* __restrict__ Bm,
    __half* __restrict__ outH, float* __restrict__ outF,
    float* __restrict__ outMf, const unsigned char* __restrict__ mask,
    const float* __restrict__ Wq32, const float* __restrict__ Wk32,
    const float* __restrict__ bq, const float* __restrict__ bk,
    float scale, int aRows, int bRows, int outLd, int nch) {
    constexpr int BMv = (MODE == 0) ? 64 : 128;
    constexpr int MI = BMv / 32;                 // 2 or 4 m16 frags per warp
    constexpr int KPRE = (MODE == 0) ? 2 : 4;    // B-preload depth (ks steps)
    constexpr int A_BYTES = BMv * 128;
    constexpr int STAGEB = A_BYTES + BN * 128;

    extern __shared__ char smem[];
    const uint32_t sb = smem_u32(smem);
    const int tid = threadIdx.x;
    const int wid = tid >> 5;
    const int l = tid & 31;
    const int wm = wid >> 2;
    const int wn = wid & 3;
    const int mt = blockIdx.x, nt = blockIdx.y, bz = blockIdx.z;

    // ---- MODE 2 extra z-slice: parallel bias-vector prep ----
    if (MODE == 2 && bz == MSPLIT) {
        const int id = mt * 4 + nt;            // 0..15
        const bool isU = id < 8;               // 0..7: wu,  8..15: wv
        const int base = (id & 7) * 64;        // 64 d-outputs per CTA
        const float* W = isU ? Wq32 : Wk32;
        const float* bb = isU ? bk : bq;
        float* dst = isU ? g_wu : g_wv;
        const int dl = tid & 63;
        const int js = tid >> 6;               // 0..3: j-range split
        const int d = base + dl;
        float s = 0.f;
        const int j0 = js * 128;
#pragma unroll 16
        for (int j = 0; j < 128; ++j)
            s += bb[j0 + j] * W[(size_t)(j0 + j) * KD + d];
        __shared__ float red[4][64];
        red[js][dl] = s;
        __syncthreads();
        if (tid < 64)
            dst[base + tid] =
                (red[0][tid] + red[1][tid]) + (red[2][tid] + red[3][tid]);
        if (id == 0 && wid == 2) {
            float cs = 0.f;
#pragma unroll
            for (int jj = l; jj < KD; jj += 32) cs += bq[jj] * bk[jj];
#pragma unroll
            for (int o = 16; o; o >>= 1)
                cs += __shfl_xor_sync(0xffffffff, cs, o);
            if (l == 0) g_c = cs;
        }
        return;
    }

    size_t aBase, bBase;
    int kStart;
    if (MODE == 2) {
        aBase = 0;
        bBase = 0;
        kStart = bz * (KD / MSPLIT);
    } else {
        aBase = ((size_t)bz * aRows + (size_t)mt * BMv) * KD;
        bBase = ((size_t)bz * bRows + (size_t)nt * BN) * KD;
        kStart = 0;
    }

    float* sv = (float*)(smem + 2 * STAGEB);
    unsigned char* sm = (unsigned char*)(smem + 2 * STAGEB + 512);
    if (MODE == 1 && tid < 128) {
        const size_t colg = (size_t)bz * S_ + (size_t)nt * BN + tid;
        sv[tid] = g_v[colg];
        sm[tid] = mask[colg];
    }

    float acc[MI][4][4];
#pragma unroll
    for (int i = 0; i < MI; ++i)
#pragma unroll
        for (int j = 0; j < 4; ++j)
#pragma unroll
            for (int c = 0; c < 4; ++c) acc[i][j][c] = 0.f;

    const int aRow = wm * (MI * 16) + (l & 15);
    const int aKsel = ((l >> 4) & 1) * 16;
    const int bRow = wn * 32 + (l & 7) + ((l >> 4) & 1) * 8;
    const int bKsel = ((l >> 3) & 1) * 16;

    // B-preload software pipeline (depth KPRE ks-steps)
    auto mma_chunk = [&](uint32_t sA, uint32_t sB) {
#pragma unroll
        for (int kb = 0; kb < BK / 16; kb += KPRE) {
            uint32_t bfr[KPRE][2][4];
#pragma unroll
            for (int k2 = 0; k2 < KPRE; ++k2)
#pragma unroll
                for (int nb = 0; nb < 2; ++nb)
                    ldsm4(bfr[k2][nb],
                          sB + SWZ((uint32_t)((bRow + nb * 16) * 128 +
                                              (kb + k2) * 32 + bKsel)));
#pragma unroll
            for (int k2 = 0; k2 < KPRE; ++k2) {
                const int ks = kb + k2;
                uint32_t afr[MI][4];
#pragma unroll
                for (int mi = 0; mi < MI; ++mi)
                    ldsm4(afr[mi],
                          sA + SWZ((uint32_t)((aRow + mi * 16) * 128 +
                                              ks * 32 + aKsel)));
#pragma unroll
                for (int mi = 0; mi < MI; ++mi)
#pragma unroll
                    for (int ni = 0; ni < 4; ++ni)
                        mma16816(acc[mi][ni], afr[mi],
                                 bfr[k2][ni >> 1][(ni & 1) * 2],
                                 bfr[k2][ni >> 1][(ni & 1) * 2 + 1]);
            }
        }
    };

    if (MODE == 2) {
        // single-buffer, direct transposed fp32 loads + convert
        const uint32_t sA = sb, sB = sb + A_BYTES;
        for (int ch = 0; ch < nch; ++ch) {
            const int k0 = kStart + ch * BK;
            __syncthreads();
#pragma unroll
            for (int t = 0; t < 32; ++t) {
                int idx = tid + t * 256;          // 8192 = 128 rows x 64 cols
                int r = idx & 127, c = idx >> 7;
                float va = Wk32[(size_t)(k0 + c) * KD + mt * 128 + r];
                float vb = Wq32[(size_t)(k0 + c) * KD + nt * 128 + r];
                *(__half*)(smem + SWZ((uint32_t)(r * 128 + c * 2))) =
                    __float2half(va);
                *(__half*)(smem + A_BYTES + SWZ((uint32_t)(r * 128 + c * 2))) =
                    __float2half(vb);
            }
            __syncthreads();
            mma_chunk(sA, sB);
        }
        __syncthreads();
    } else {
        auto load_tile = [&](int stg, int k0) {
            const uint32_t sA = sb + stg * STAGEB;
            const uint32_t sB = sA + A_BYTES;
#pragma unroll
            for (int t = 0; t < BMv / 32; ++t) {
                int i = tid + t * 256;
                int r = i >> 3, c = i & 7;
                cp16(sA + SWZ((uint32_t)(r * 128 + c * 16)),
                     A + aBase + (size_t)r * KD + k0 + c * 8);
            }
#pragma unroll
            for (int t = 0; t < 4; ++t) {
                int i = tid + t * 256;
                int r = i >> 3, c = i & 7;
                cp16(sB + SWZ((uint32_t)(r * 128 + c * 16)),
                     Bm + bBase + (size_t)r * KD + k0 + c * 8);
            }
        };

        load_tile(0, kStart);
        CP_COMMIT();

        int stg = 0;
        for (int ch = 0; ch < nch; ++ch) {
            if (ch + 1 < nch) {
                load_tile(stg ^ 1, kStart + (ch + 1) * BK);
                CP_COMMIT();
                CP_WAIT1();
            } else {
                CP_WAIT0();
            }
            __syncthreads();
            mma_chunk(sb + stg * STAGEB, sb + stg * STAGEB + A_BYTES);
            __syncthreads();
            stg ^= 1;
        }
    }

    // ---------------- epilogue ----------------
    const int gid = l >> 2, tig = l & 3;
#pragma unroll
    for (int mi = 0; mi < MI; ++mi) {
#pragma unroll
        for (int h = 0; h < 2; ++h) {
            const int row = mt * BMv + wm * (MI * 16) + mi * 16 + gid + h * 8;
            const size_t rowg =
                (MODE == 2) ? (size_t)row : (size_t)bz * aRows + row;
            float uu = 0.f;
            if (MODE == 1) uu = g_u[rowg];
#pragma unroll
            for (int ni = 0; ni < 4; ++ni) {
                const int lcol = wn * 32 + ni * 8 + tig * 2;
                const int col = nt * BN + lcol;
                const float v0 = acc[mi][ni][h * 2 + 0];
                const float v1 = acc[mi][ni][h * 2 + 1];
                if (MODE == 0) {
                    *(__half2*)(outH + rowg * outLd + col) =
                        __floats2half2_rn(v0 * scale, v1 * scale);
                } else if (MODE == 2) {
                    float* dst = outMf + (size_t)bz * (KD * KD) +
                                 rowg * outLd + col;
                    dst[0] = v0;
                    dst[1] = v1;
                } else {
                    const float NEG_INF = __int_as_float(0xff800000);
                    float2 o;
                    o.x = sm[lcol + 0] ? NEG_INF : v0 + uu + sv[lcol + 0];
                    o.y = sm[lcol + 1] ? NEG_INF : v1 + uu + sv[lcol + 1];
                    __stcs((float2*)(outF + rowg * (size_t)S_ + col), o);
                }
            }
        }
    }
}

// ---------------- host launch ----------------
extern "C" void kernel_launch(void* const* d_in, const int* in_sizes, int n_in,
                              void* d_out, int out_size) {
    const float* query = (const float*)d_in[0];
    const float* keys = (const float*)d_in[1];
    const unsigned char* mask = (const unsigned char*)d_in[2];
    const float* q_w = (const float*)d_in[3];
    const float* q_b = (const float*)d_in[4];
    const float* k_w = (const float*)d_in[5];
    const float* k_b = (const float*)d_in[6];

    void *xq16, *xk16, *Mf, *M, *Y;
    cudaGetSymbolAddress(&xq16, g_xq16);
    cudaGetSymbolAddress(&xk16, g_xk16);
    cudaGetSymbolAddress(&Mf, g_Mf);
    cudaGetSymbolAddress(&M, g_M);
    cudaGetSymbolAddress(&Y, g_Y);

    const int SMEM0 = 2 * (64 * 128 + BN * 128) + 640;     // 49792
    const int SMEM1 = 2 * (128 * 128 + BN * 128) + 640;    // 66176
    const int SMEM2 = 128 * 128 + BN * 128;                // 32768

    cudaFuncSetAttribute(hgemm<0>, cudaFuncAttributeMaxDynamicSharedMemorySize,
                         SMEM0);
    cudaFuncSetAttribute(hgemm<1>, cudaFuncAttributeMaxDynamicSharedMemorySize,
                         SMEM1);
    cudaFuncSetAttribute(hgemm<2>, cudaFuncAttributeMaxDynamicSharedMemorySize,
                         SMEM2);

    // 1) M split-K partials (z=0..3, direct fp32 weight loads)
    //    + parallel bias-vector prep wu, wv, c (z=4, 16 CTAs)
    hgemm<2><<<dim3(KD / 128, KD / BN, MSPLIT + 1), 256, SMEM2>>>(
        nullptr, nullptr, nullptr, nullptr, (float*)Mf, nullptr,
        q_w, k_w, q_b, k_b, 1.0f, KD, KD, KD, (KD / MSPLIT) / BK);

    // 2) fused: convert xq/xk + row GEMVs u,v + M partial reduce -> fp16
    conv_fused<<<CONV_BLOCKS + MCVT_BLOCKS, 256>>>((const float4*)query,
                                                   (const float4*)keys);

    // 3) Y = (xq @ M)/64   [8192 x 512] fp16, BM=64, 3 CTA/SM
    hgemm<0><<<dim3(MQ_ / 64, KD / BN, 1), 256, SMEM0>>>(
        (const __half*)xq16, (const __half*)M, (__half*)Y, nullptr, nullptr,
        nullptr, nullptr, nullptr, nullptr, nullptr,
        0.015625f, MQ_, KD, KD, KD / BK);

    // 4) logits = Y @ xk^T + u[t] + v[s], masked   [4,2048,4096] fp32
    hgemm<1><<<dim3(T_ / 128, S_ / BN, B_), 256, SMEM1>>>(
        (const __half*)Y, (const __half*)xk16, nullptr, (float*)d_out, nullptr,
        mask, nullptr, nullptr, nullptr, nullptr,
        1.0f, T_, S_, S_, KD / BK);
}